// round 3
// baseline (speedup 1.0000x reference)
#include <cuda_runtime.h>

#define NNODES 50000
#define NEDGES 800000
#define NB 4
#define NIN 32
#define H2 30

// ---------------- device scratch (static, no allocations; 16B-aligned for v4 access) ----------------
__device__ double g_stats[2];                                   // sum, sumsq of edge_attr
__device__ float  g_norm[2];                                    // mean, inv_std
__device__ int    g_is64;                                       // edge_index dtype flag
__device__ int    g_src[NEDGES];                                // converted int32 indices
__device__ int    g_tgt[NEDGES];
__device__ __align__(16) float g_P[NB * NNODES * 32];           // x @ W1[0:32,:]
__device__ __align__(16) float g_Q[NB * NNODES * 32];           // x @ W1[32:64,:] + b1
__device__ __align__(16) float g_acc[NB * NNODES * 32];         // segment-sum acc (30 used, pad 32)

__device__ __forceinline__ float sigm(float x) {
    return __fdividef(1.0f, 1.0f + __expf(-x));
}

// ---------------- 0. index dtype detect + convert ----------------
__global__ void k_detect(const int* __restrict__ ei) {
    // int64 little-endian indices < 50000 => every odd 32-bit word is 0.
    int odd_or = 0;
    for (int k = 1; k < 128; k += 2) odd_or |= ei[k];
    g_is64 = (odd_or == 0) ? 1 : 0;
}

__global__ void k_convert(const int* __restrict__ ei) {
    int e = blockIdx.x * 256 + threadIdx.x;
    if (e >= NEDGES) return;
    int s, t;
    if (g_is64) {
        const long long* e64 = (const long long*)ei;
        s = (int)e64[e];
        t = (int)e64[NEDGES + e];
    } else {
        s = ei[e];
        t = ei[NEDGES + e];
    }
    // clamp defensively: any surprise becomes rel_err, not a crash
    s = min(max(s, 0), NNODES - 1);
    t = min(max(t, 0), NNODES - 1);
    g_src[e] = s;
    g_tgt[e] = t;
}

// ---------------- 1. stats ----------------
__global__ void k_zero_stats() {
    g_stats[0] = 0.0;
    g_stats[1] = 0.0;
}

__global__ void k_reduce_ea(const float* __restrict__ ea) {
    __shared__ float s1[256], s2[256];
    int i = blockIdx.x * 256 + threadIdx.x;
    float v = (i < NEDGES) ? ea[i] : 0.0f;
    s1[threadIdx.x] = v;
    s2[threadIdx.x] = v * v;
    __syncthreads();
    for (int o = 128; o > 0; o >>= 1) {
        if (threadIdx.x < o) {
            s1[threadIdx.x] += s1[threadIdx.x + o];
            s2[threadIdx.x] += s2[threadIdx.x + o];
        }
        __syncthreads();
    }
    if (threadIdx.x == 0) {
        atomicAdd(&g_stats[0], (double)s1[0]);
        atomicAdd(&g_stats[1], (double)s2[0]);
    }
}

__global__ void k_finalize_stats() {
    double s = g_stats[0], ss = g_stats[1];
    double n = (double)NEDGES;
    double mean = s / n;
    double var = (ss - s * s / n) / (n - 1.0);   // ddof = 1
    g_norm[0] = (float)mean;
    g_norm[1] = (float)(1.0 / sqrt(var));
}

// ---------------- 2. per-node precompute: P = x@W1a, Q = x@W1b + b1 ----------------
__global__ void k_precompute(const float* __restrict__ x,
                             const float* __restrict__ W1,
                             const float* __restrict__ b1) {
    int tid = blockIdx.x * 256 + threadIdx.x;       // over NB*NNODES*32
    if (tid >= NB * NNODES * 32) return;
    int j   = tid & 31;
    int row = tid >> 5;                              // b*N + n
    const float* xr = x + (size_t)row * NIN;
    float p = 0.0f;
    float q = b1[j];
    #pragma unroll
    for (int i = 0; i < NIN; i++) {
        float xi = __ldg(&xr[i]);                    // broadcast across j-lanes
        p = fmaf(xi, __ldg(&W1[i * 32 + j]), p);
        q = fmaf(xi, __ldg(&W1[(32 + i) * 32 + j]), q);
    }
    g_P[tid] = p;
    g_Q[tid] = q;
}

// ---------------- 3. zero accumulator ----------------
__global__ void k_zero_acc() {
    int tid = blockIdx.x * 256 + threadIdx.x;        // over (NB*NNODES*32)/4
    if (tid < NB * NNODES * 8) {
        ((float4*)g_acc)[tid] = make_float4(0.f, 0.f, 0.f, 0.f);
    }
}

// ---------------- 4. edge kernel ----------------
__global__ __launch_bounds__(256) void k_edge(const float* __restrict__ ea,
                                              const float* __restrict__ W1,
                                              const float* __restrict__ W2,
                                              const float* __restrict__ b2) {
    __shared__ __align__(16) float sW2[32 * 32];   // [j][k], k padded to 32 with zeros
    __shared__ __align__(16) float sw1c[32];
    __shared__ __align__(16) float sb2[32];

    for (int idx = threadIdx.x; idx < 1024; idx += 256) {
        int j = idx >> 5, k = idx & 31;
        sW2[idx] = (k < H2) ? W2[j * H2 + k] : 0.0f;
    }
    if (threadIdx.x < 32) {
        sw1c[threadIdx.x] = W1[64 * 32 + threadIdx.x];
        sb2[threadIdx.x]  = (threadIdx.x < H2) ? b2[threadIdx.x] : 0.0f;
    }
    __syncthreads();

    int e = blockIdx.x * 256 + threadIdx.x;
    if (e >= NEDGES) return;
    int b = blockIdx.y;

    int src = g_src[e];
    int tgt = g_tgt[e];
    float ean = (ea[e] - g_norm[0]) * g_norm[1];

    const float4* Pr = (const float4*)&g_P[((size_t)b * NNODES + src) * 32];
    const float4* Qr = (const float4*)&g_Q[((size_t)b * NNODES + tgt) * 32];

    float z1[32];
    #pragma unroll
    for (int m = 0; m < 8; m++) {
        float4 pv = Pr[m];
        float4 qv = Qr[m];
        z1[4 * m + 0] = pv.x + qv.x + ean * sw1c[4 * m + 0];
        z1[4 * m + 1] = pv.y + qv.y + ean * sw1c[4 * m + 1];
        z1[4 * m + 2] = pv.z + qv.z + ean * sw1c[4 * m + 2];
        z1[4 * m + 3] = pv.w + qv.w + ean * sw1c[4 * m + 3];
    }

    float h2[32];
    #pragma unroll
    for (int k = 0; k < 32; k++) h2[k] = sb2[k];

    #pragma unroll
    for (int j = 0; j < 32; j++) {
        float a = sigm(z1[j]);
        const float4* wr = (const float4*)&sW2[j * 32];
        #pragma unroll
        for (int m = 0; m < 8; m++) {
            float4 w = wr[m];
            h2[4 * m + 0] = fmaf(a, w.x, h2[4 * m + 0]);
            h2[4 * m + 1] = fmaf(a, w.y, h2[4 * m + 1]);
            h2[4 * m + 2] = fmaf(a, w.z, h2[4 * m + 2]);
            h2[4 * m + 3] = fmaf(a, w.w, h2[4 * m + 3]);
        }
    }

    #pragma unroll
    for (int k = 0; k < H2; k++) h2[k] = sigm(h2[k]);
    h2[30] = 0.0f;
    h2[31] = 0.0f;

    float4* at = (float4*)&g_acc[((size_t)b * NNODES + tgt) * 32];
    float4* as = (float4*)&g_acc[((size_t)b * NNODES + src) * 32];
    #pragma unroll
    for (int m = 0; m < 8; m++) {
        float4 hv = make_float4(h2[4 * m + 0], h2[4 * m + 1], h2[4 * m + 2], h2[4 * m + 3]);
        atomicAdd(at + m, hv);
        atomicAdd(as + m, make_float4(-hv.x, -hv.y, -hv.z, -hv.w));
    }
}

// ---------------- 5. epilogue: out = sigmoid(acc @ W3 + b3) ----------------
__global__ void k_out(const float* __restrict__ W3,
                      const float* __restrict__ b3,
                      float* __restrict__ out) {
    int tid = blockIdx.x * 256 + threadIdx.x;        // over NB*NNODES*32
    if (tid >= NB * NNODES * 32) return;
    int j   = tid & 31;
    int row = tid >> 5;
    const float* ar = &g_acc[(size_t)row * 32];
    float o = b3[j];
    #pragma unroll
    for (int k = 0; k < H2; k++) {
        o = fmaf(ar[k], __ldg(&W3[k * 32 + j]), o);  // ar[k] broadcast across lanes
    }
    out[tid] = sigm(o);
}

// ---------------- launch ----------------
extern "C" void kernel_launch(void* const* d_in, const int* in_sizes, int n_in,
                              void* d_out, int out_size) {
    // Resolve inputs by element count (robust to metadata ordering).
    const void* p_x = 0;  const void* p_ei = 0; const void* p_ea = 0;
    const void* p_W1 = 0; const void* p_b1 = 0; const void* p_W2 = 0;
    const void* p_b2 = 0; const void* p_W3 = 0; const void* p_b3 = 0;
    for (int i = 0; i < n_in; i++) {
        int s = in_sizes[i];
        const void* p = d_in[i];
        if      (s == NB * NNODES * NIN)  p_x = p;
        else if (s == 2 * NEDGES)         p_ei = p;
        else if (s == NEDGES)             p_ea = p;
        else if (s == (2 * NIN + 1) * 32) p_W1 = p;
        else if (s == 32 * H2)            { if (!p_W2) p_W2 = p; else p_W3 = p; }  // W2 then W3
        else if (s == 32)                 { if (!p_b1) p_b1 = p; else p_b3 = p; }  // b1 then b3
        else if (s == H2)                 p_b2 = p;
    }
    const float* x  = (const float*)p_x;
    const int*   ei = (const int*)p_ei;
    const float* ea = (const float*)p_ea;
    const float* W1 = (const float*)p_W1;
    const float* b1 = (const float*)p_b1;
    const float* W2 = (const float*)p_W2;
    const float* b2 = (const float*)p_b2;
    const float* W3 = (const float*)p_W3;
    const float* b3 = (const float*)p_b3;
    float* out = (float*)d_out;

    k_detect<<<1, 1>>>(ei);
    k_convert<<<(NEDGES + 255) / 256, 256>>>(ei);
    k_zero_stats<<<1, 1>>>();
    k_reduce_ea<<<(NEDGES + 255) / 256, 256>>>(ea);
    k_finalize_stats<<<1, 1>>>();
    k_precompute<<<(NB * NNODES * 32 + 255) / 256, 256>>>(x, W1, b1);
    k_zero_acc<<<(NB * NNODES * 8 + 255) / 256, 256>>>();
    dim3 egrid((NEDGES + 255) / 256, NB);
    k_edge<<<egrid, 256>>>(ea, W1, W2, b2);
    k_out<<<(NB * NNODES * 32 + 255) / 256, 256>>>(W3, b3, out);
}

// round 4
// speedup vs baseline: 1.1223x; 1.1223x over previous
#include <cuda_runtime.h>
#include <cuda_bf16.h>

#define NNODES 50000
#define NEDGES 800000
#define NB 4
#define NIN 32
#define H2 30

typedef unsigned long long ull;

// ---------------- device scratch (static; 16B-aligned for v4 access) ----------------
__device__ double g_stats[2];
__device__ float  g_norm[2];
__device__ int    g_is64;
__device__ int    g_src[NEDGES];
__device__ int    g_tgt[NEDGES];
__device__ __align__(16) __nv_bfloat16 g_Pb[NB * NNODES * 32];   // bf16 x@W1a
__device__ __align__(16) __nv_bfloat16 g_Qb[NB * NNODES * 32];   // bf16 x@W1b + b1
__device__ __align__(16) float g_acc[NB * NNODES * 32];          // fp32 segment acc (30 used)

__device__ __forceinline__ float sigm(float x) {            // exact-ish (epilogue)
    return __fdividef(1.0f, 1.0f + __expf(-x));
}
__device__ __forceinline__ float sigm_fast(float x) {       // 1 MUFU (interior)
    float t;
    asm("tanh.approx.f32 %0, %1;" : "=f"(t) : "f"(x * 0.5f));
    return fmaf(0.5f, t, 0.5f);
}
__device__ __forceinline__ ull pack2(float lo, float hi) {
    ull r;
    asm("mov.b64 %0, {%1,%2};" : "=l"(r) : "r"(__float_as_uint(lo)), "r"(__float_as_uint(hi)));
    return r;
}

// ---------------- 0. index dtype detect + convert ----------------
__global__ void k_detect(const int* __restrict__ ei) {
    int odd_or = 0;
    for (int k = 1; k < 128; k += 2) odd_or |= ei[k];
    g_is64 = (odd_or == 0) ? 1 : 0;
}

__global__ void k_convert(const int* __restrict__ ei) {
    int e = blockIdx.x * 256 + threadIdx.x;
    if (e >= NEDGES) return;
    int s, t;
    if (g_is64) {
        const long long* e64 = (const long long*)ei;
        s = (int)e64[e];
        t = (int)e64[NEDGES + e];
    } else {
        s = ei[e];
        t = ei[NEDGES + e];
    }
    s = min(max(s, 0), NNODES - 1);
    t = min(max(t, 0), NNODES - 1);
    g_src[e] = s;
    g_tgt[e] = t;
}

// ---------------- 1. stats ----------------
__global__ void k_zero_stats() { g_stats[0] = 0.0; g_stats[1] = 0.0; }

__global__ void k_reduce_ea(const float* __restrict__ ea) {
    __shared__ float s1[256], s2[256];
    int i = blockIdx.x * 256 + threadIdx.x;
    float v = (i < NEDGES) ? ea[i] : 0.0f;
    s1[threadIdx.x] = v;
    s2[threadIdx.x] = v * v;
    __syncthreads();
    for (int o = 128; o > 0; o >>= 1) {
        if (threadIdx.x < o) {
            s1[threadIdx.x] += s1[threadIdx.x + o];
            s2[threadIdx.x] += s2[threadIdx.x + o];
        }
        __syncthreads();
    }
    if (threadIdx.x == 0) {
        atomicAdd(&g_stats[0], (double)s1[0]);
        atomicAdd(&g_stats[1], (double)s2[0]);
    }
}

__global__ void k_finalize_stats() {
    double s = g_stats[0], ss = g_stats[1];
    double n = (double)NEDGES;
    double mean = s / n;
    double var = (ss - s * s / n) / (n - 1.0);   // ddof = 1
    g_norm[0] = (float)mean;
    g_norm[1] = (float)(1.0 / sqrt(var));
}

// ---------------- 2. per-node precompute (bf16 out) ----------------
__global__ void k_precompute(const float* __restrict__ x,
                             const float* __restrict__ W1,
                             const float* __restrict__ b1) {
    int tid = blockIdx.x * 256 + threadIdx.x;
    if (tid >= NB * NNODES * 32) return;
    int j   = tid & 31;
    int row = tid >> 5;
    const float* xr = x + (size_t)row * NIN;
    float p = 0.0f;
    float q = b1[j];
    #pragma unroll
    for (int i = 0; i < NIN; i++) {
        float xi = __ldg(&xr[i]);
        p = fmaf(xi, __ldg(&W1[i * 32 + j]), p);
        q = fmaf(xi, __ldg(&W1[(32 + i) * 32 + j]), q);
    }
    g_Pb[tid] = __float2bfloat16(p);
    g_Qb[tid] = __float2bfloat16(q);
}

// ---------------- 3. zero accumulator ----------------
__global__ void k_zero_acc() {
    int tid = blockIdx.x * 256 + threadIdx.x;
    if (tid < NB * NNODES * 8) {
        ((float4*)g_acc)[tid] = make_float4(0.f, 0.f, 0.f, 0.f);
    }
}

// ---------------- 4. edge kernel ----------------
__global__ __launch_bounds__(256) void k_edge(const float* __restrict__ ea,
                                              const float* __restrict__ W1,
                                              const float* __restrict__ W2,
                                              const float* __restrict__ b2) {
    __shared__ __align__(16) ull sW2p[32 * 16];   // [j][m]: (W2[j][2m], W2[j][2m+1]), zero-padded
    __shared__ float sw1c[32];
    __shared__ ull   sb2p[16];

    for (int idx = threadIdx.x; idx < 512; idx += 256) {
        int j = idx >> 4, m = idx & 15;
        int k0 = 2 * m, k1 = 2 * m + 1;
        float w0 = (k0 < H2) ? W2[j * H2 + k0] : 0.0f;
        float w1 = (k1 < H2) ? W2[j * H2 + k1] : 0.0f;
        sW2p[idx] = pack2(w0, w1);
    }
    if (threadIdx.x < 32) {
        sw1c[threadIdx.x] = W1[64 * 32 + threadIdx.x];
    }
    if (threadIdx.x < 16) {
        int m = threadIdx.x;
        float d0 = (2 * m     < H2) ? b2[2 * m]     : 0.0f;
        float d1 = (2 * m + 1 < H2) ? b2[2 * m + 1] : 0.0f;
        sb2p[m] = pack2(d0, d1);
    }
    __syncthreads();

    int e = blockIdx.x * 256 + threadIdx.x;
    if (e >= NEDGES) return;
    int b = blockIdx.y;

    int src = g_src[e];
    int tgt = g_tgt[e];
    float ean = (ea[e] - g_norm[0]) * g_norm[1];

    // gather bf16 rows (64B each = 4 x LDG.128)
    const uint4* Pr = (const uint4*)(g_Pb + ((size_t)b * NNODES + src) * 32);
    const uint4* Qr = (const uint4*)(g_Qb + ((size_t)b * NNODES + tgt) * 32);
    uint4 pv[4], qv[4];
    #pragma unroll
    for (int m = 0; m < 4; m++) { pv[m] = Pr[m]; qv[m] = Qr[m]; }

    const __nv_bfloat162* pb = (const __nv_bfloat162*)pv;
    const __nv_bfloat162* qb = (const __nv_bfloat162*)qv;

    float z1[32];
    #pragma unroll
    for (int m = 0; m < 16; m++) {
        float2 pf = __bfloat1622float2(pb[m]);
        float2 qf = __bfloat1622float2(qb[m]);
        z1[2 * m + 0] = pf.x + qf.x + ean * sw1c[2 * m + 0];
        z1[2 * m + 1] = pf.y + qf.y + ean * sw1c[2 * m + 1];
    }

    ull h2p[16];
    #pragma unroll
    for (int m = 0; m < 16; m++) h2p[m] = sb2p[m];

    #pragma unroll
    for (int j = 0; j < 32; j++) {
        float a = sigm_fast(z1[j]);
        ull ap;
        asm("mov.b64 %0, {%1,%1};" : "=l"(ap) : "r"(__float_as_uint(a)));
        const ull* wr = &sW2p[j * 16];
        #pragma unroll
        for (int m = 0; m < 16; m++) {
            asm("fma.rn.f32x2 %0, %1, %2, %0;" : "+l"(h2p[m]) : "l"(ap), "l"(wr[m]));
        }
    }

    float h2[32];
    #pragma unroll
    for (int m = 0; m < 16; m++) {
        unsigned lo, hi;
        asm("mov.b64 {%0,%1}, %2;" : "=r"(lo), "=r"(hi) : "l"(h2p[m]));
        h2[2 * m + 0] = sigm_fast(__uint_as_float(lo));
        h2[2 * m + 1] = sigm_fast(__uint_as_float(hi));
    }
    h2[30] = 0.0f;   // pad channels: sigmoid(0)=0.5 must not be scattered
    h2[31] = 0.0f;

    float4* at = (float4*)&g_acc[((size_t)b * NNODES + tgt) * 32];
    float4* as = (float4*)&g_acc[((size_t)b * NNODES + src) * 32];
    #pragma unroll
    for (int m = 0; m < 8; m++) {
        float4 hv = make_float4(h2[4 * m + 0], h2[4 * m + 1], h2[4 * m + 2], h2[4 * m + 3]);
        atomicAdd(at + m, hv);
        atomicAdd(as + m, make_float4(-hv.x, -hv.y, -hv.z, -hv.w));
    }
}

// ---------------- 5. epilogue: out = sigmoid(acc @ W3 + b3) ----------------
__global__ void k_out(const float* __restrict__ W3,
                      const float* __restrict__ b3,
                      float* __restrict__ out) {
    int tid = blockIdx.x * 256 + threadIdx.x;
    if (tid >= NB * NNODES * 32) return;
    int j   = tid & 31;
    int row = tid >> 5;
    const float* ar = &g_acc[(size_t)row * 32];
    float o = b3[j];
    #pragma unroll
    for (int k = 0; k < H2; k++) {
        o = fmaf(ar[k], __ldg(&W3[k * 32 + j]), o);
    }
    out[tid] = sigm(o);
}

// ---------------- launch ----------------
extern "C" void kernel_launch(void* const* d_in, const int* in_sizes, int n_in,
                              void* d_out, int out_size) {
    const void* p_x = 0;  const void* p_ei = 0; const void* p_ea = 0;
    const void* p_W1 = 0; const void* p_b1 = 0; const void* p_W2 = 0;
    const void* p_b2 = 0; const void* p_W3 = 0; const void* p_b3 = 0;
    for (int i = 0; i < n_in; i++) {
        int s = in_sizes[i];
        const void* p = d_in[i];
        if      (s == NB * NNODES * NIN)  p_x = p;
        else if (s == 2 * NEDGES)         p_ei = p;
        else if (s == NEDGES)             p_ea = p;
        else if (s == (2 * NIN + 1) * 32) p_W1 = p;
        else if (s == 32 * H2)            { if (!p_W2) p_W2 = p; else p_W3 = p; }
        else if (s == 32)                 { if (!p_b1) p_b1 = p; else p_b3 = p; }
        else if (s == H2)                 p_b2 = p;
    }
    const float* x  = (const float*)p_x;
    const int*   ei = (const int*)p_ei;
    const float* ea = (const float*)p_ea;
    const float* W1 = (const float*)p_W1;
    const float* b1 = (const float*)p_b1;
    const float* W2 = (const float*)p_W2;
    const float* b2 = (const float*)p_b2;
    const float* W3 = (const float*)p_W3;
    const float* b3 = (const float*)p_b3;
    float* out = (float*)d_out;

    k_detect<<<1, 1>>>(ei);
    k_convert<<<(NEDGES + 255) / 256, 256>>>(ei);
    k_zero_stats<<<1, 1>>>();
    k_reduce_ea<<<(NEDGES + 255) / 256, 256>>>(ea);
    k_finalize_stats<<<1, 1>>>();
    k_precompute<<<(NB * NNODES * 32 + 255) / 256, 256>>>(x, W1, b1);
    k_zero_acc<<<(NB * NNODES * 8 + 255) / 256, 256>>>();
    dim3 egrid((NEDGES + 255) / 256, NB);
    k_edge<<<egrid, 256>>>(ea, W1, W2, b2);
    k_out<<<(NB * NNODES * 32 + 255) / 256, 256>>>(W3, b3, out);
}

// round 5
// speedup vs baseline: 1.1977x; 1.0672x over previous
#include <cuda_runtime.h>
#include <cuda_bf16.h>

#define NNODES 50000
#define NEDGES 800000
#define NB 4
#define NIN 32
#define H2 30

typedef unsigned long long ull;

// ---------------- device scratch ----------------
__device__ double g_stats[2];
__device__ float  g_norm[2];
__device__ int    g_is64;
__device__ int    g_src[NEDGES];
__device__ int    g_tgt[NEDGES];
__device__ __align__(16) __nv_bfloat16 g_Pb[NB * NNODES * 32];
__device__ __align__(16) __nv_bfloat16 g_Qb[NB * NNODES * 32];
__device__ __align__(16) float g_acc[NB * NNODES * 32];

__device__ __forceinline__ float sigm(float x) {            // epilogue (accuracy)
    return __fdividef(1.0f, 1.0f + __expf(-x));
}
__device__ __forceinline__ float sigm_fast(float x) {       // 1 MUFU
    float t;
    asm("tanh.approx.f32 %0, %1;" : "=f"(t) : "f"(x * 0.5f));
    return fmaf(0.5f, t, 0.5f);
}
__device__ __forceinline__ ull pack2(float lo, float hi) {
    ull r;
    asm("mov.b64 %0, {%1,%2};" : "=l"(r) : "r"(__float_as_uint(lo)), "r"(__float_as_uint(hi)));
    return r;
}

// ---------------- 1. detect + zero stats ----------------
__global__ void k_detect(const int* __restrict__ ei) {
    int odd_or = 0;
    for (int k = 1; k < 128; k += 2) odd_or |= ei[k];
    g_is64 = (odd_or == 0) ? 1 : 0;
    g_stats[0] = 0.0;
    g_stats[1] = 0.0;
}

// ---------------- 2. convert indices ----------------
__global__ void k_convert(const int* __restrict__ ei) {
    int e = blockIdx.x * 256 + threadIdx.x;
    if (e >= NEDGES) return;
    int s, t;
    if (g_is64) {
        const long long* e64 = (const long long*)ei;
        s = (int)e64[e];
        t = (int)e64[NEDGES + e];
    } else {
        s = ei[e];
        t = ei[NEDGES + e];
    }
    s = min(max(s, 0), NNODES - 1);
    t = min(max(t, 0), NNODES - 1);
    g_src[e] = s;
    g_tgt[e] = t;
}

// ---------------- 3. reduce edge_attr ----------------
__global__ void k_reduce_ea(const float* __restrict__ ea) {
    __shared__ float s1[256], s2[256];
    int i = blockIdx.x * 256 + threadIdx.x;
    float v = (i < NEDGES) ? ea[i] : 0.0f;
    s1[threadIdx.x] = v;
    s2[threadIdx.x] = v * v;
    __syncthreads();
    for (int o = 128; o > 0; o >>= 1) {
        if (threadIdx.x < o) {
            s1[threadIdx.x] += s1[threadIdx.x + o];
            s2[threadIdx.x] += s2[threadIdx.x + o];
        }
        __syncthreads();
    }
    if (threadIdx.x == 0) {
        atomicAdd(&g_stats[0], (double)s1[0]);
        atomicAdd(&g_stats[1], (double)s2[0]);
    }
}

// ---------------- 4. finalize stats ----------------
__global__ void k_finalize_stats() {
    double s = g_stats[0], ss = g_stats[1];
    double n = (double)NEDGES;
    double mean = s / n;
    double var = (ss - s * s / n) / (n - 1.0);   // ddof=1
    g_norm[0] = (float)mean;
    g_norm[1] = (float)(1.0 / sqrt(var));
}

// ---------------- 5. precompute P/Q (bf16) + zero acc ----------------
__global__ void k_precompute(const float* __restrict__ x,
                             const float* __restrict__ W1,
                             const float* __restrict__ b1) {
    int tid = blockIdx.x * 256 + threadIdx.x;
    if (tid >= NB * NNODES * 32) return;
    int j   = tid & 31;
    int row = tid >> 5;
    const float* xr = x + (size_t)row * NIN;
    float p = 0.0f;
    float q = b1[j];
    #pragma unroll
    for (int i = 0; i < NIN; i++) {
        float xi = __ldg(&xr[i]);
        p = fmaf(xi, __ldg(&W1[i * 32 + j]), p);
        q = fmaf(xi, __ldg(&W1[(32 + i) * 32 + j]), q);
    }
    g_Pb[tid] = __float2bfloat16(p);
    g_Qb[tid] = __float2bfloat16(q);
    g_acc[tid] = 0.0f;
}

// ---------------- 6. edge kernel (profiled slot) ----------------
__global__ __launch_bounds__(256) void k_edge(const float* __restrict__ ea,
                                              const float* __restrict__ W1,
                                              const float* __restrict__ W2,
                                              const float* __restrict__ b2) {
    __shared__ __align__(16) float4 sW2v[32 * 8];   // [j][m4]: 4 consecutive k, zero-padded
    __shared__ float sw1c[32];
    __shared__ ull   sb2p[16];

    for (int idx = threadIdx.x; idx < 256; idx += 256) {
        int j = idx >> 3, m = idx & 7;
        float w0 = (4 * m + 0 < H2) ? W2[j * H2 + 4 * m + 0] : 0.0f;
        float w1 = (4 * m + 1 < H2) ? W2[j * H2 + 4 * m + 1] : 0.0f;
        float w2 = (4 * m + 2 < H2) ? W2[j * H2 + 4 * m + 2] : 0.0f;
        float w3 = (4 * m + 3 < H2) ? W2[j * H2 + 4 * m + 3] : 0.0f;
        sW2v[idx] = make_float4(w0, w1, w2, w3);
    }
    if (threadIdx.x < 32) {
        sw1c[threadIdx.x] = W1[64 * 32 + threadIdx.x];
    }
    if (threadIdx.x < 16) {
        int m = threadIdx.x;
        float d0 = (2 * m     < H2) ? b2[2 * m]     : 0.0f;
        float d1 = (2 * m + 1 < H2) ? b2[2 * m + 1] : 0.0f;
        sb2p[m] = pack2(d0, d1);
    }
    __syncthreads();

    int e = blockIdx.x * 256 + threadIdx.x;
    if (e >= NEDGES) return;
    int b = blockIdx.y;

    int src = g_src[e];
    int tgt = g_tgt[e];
    float ean = (ea[e] - g_norm[0]) * g_norm[1];

    const uint4* Pr = (const uint4*)(g_Pb + ((size_t)b * NNODES + src) * 32);
    const uint4* Qr = (const uint4*)(g_Qb + ((size_t)b * NNODES + tgt) * 32);
    uint4 pv[4], qv[4];
    #pragma unroll
    for (int m = 0; m < 4; m++) { pv[m] = Pr[m]; qv[m] = Qr[m]; }

    const __nv_bfloat162* pb = (const __nv_bfloat162*)pv;
    const __nv_bfloat162* qb = (const __nv_bfloat162*)qv;

    float z1[32];
    #pragma unroll
    for (int m = 0; m < 16; m++) {
        float2 pf = __bfloat1622float2(pb[m]);
        float2 qf = __bfloat1622float2(qb[m]);
        z1[2 * m + 0] = pf.x + qf.x + ean * sw1c[2 * m + 0];
        z1[2 * m + 1] = pf.y + qf.y + ean * sw1c[2 * m + 1];
    }

    ull h2p[16];
    #pragma unroll
    for (int m = 0; m < 16; m++) h2p[m] = sb2p[m];

    #pragma unroll
    for (int j = 0; j < 32; j++) {
        float a = sigm_fast(z1[j]);
        ull ap;
        asm("mov.b64 %0, {%1,%1};" : "=l"(ap) : "r"(__float_as_uint(a)));
        const float4* wr = &sW2v[j * 8];
        #pragma unroll
        for (int m = 0; m < 8; m++) {
            float4 w = wr[m];                       // LDS.128: 2 f32x2 pairs
            ull w01 = pack2(w.x, w.y);
            ull w23 = pack2(w.z, w.w);
            asm("fma.rn.f32x2 %0, %1, %2, %0;" : "+l"(h2p[2 * m + 0]) : "l"(ap), "l"(w01));
            asm("fma.rn.f32x2 %0, %1, %2, %0;" : "+l"(h2p[2 * m + 1]) : "l"(ap), "l"(w23));
        }
    }

    float h2[32];
    #pragma unroll
    for (int m = 0; m < 16; m++) {
        unsigned lo, hi;
        asm("mov.b64 {%0,%1}, %2;" : "=r"(lo), "=r"(hi) : "l"(h2p[m]));
        h2[2 * m + 0] = sigm_fast(__uint_as_float(lo));
        h2[2 * m + 1] = sigm_fast(__uint_as_float(hi));
    }
    h2[30] = 0.0f;   // pad channels must not scatter sigmoid(0)
    h2[31] = 0.0f;

    float4* at = (float4*)&g_acc[((size_t)b * NNODES + tgt) * 32];
    float4* as = (float4*)&g_acc[((size_t)b * NNODES + src) * 32];
    #pragma unroll
    for (int m = 0; m < 8; m++) {
        float4 hv = make_float4(h2[4 * m + 0], h2[4 * m + 1], h2[4 * m + 2], h2[4 * m + 3]);
        atomicAdd(at + m, hv);
        atomicAdd(as + m, make_float4(-hv.x, -hv.y, -hv.z, -hv.w));
    }
}

// ---------------- 7. epilogue ----------------
__global__ void k_out(const float* __restrict__ W3,
                      const float* __restrict__ b3,
                      float* __restrict__ out) {
    int tid = blockIdx.x * 256 + threadIdx.x;
    if (tid >= NB * NNODES * 32) return;
    int j   = tid & 31;
    int row = tid >> 5;
    const float* ar = &g_acc[(size_t)row * 32];
    float o = b3[j];
    #pragma unroll
    for (int k = 0; k < H2; k++) {
        o = fmaf(ar[k], __ldg(&W3[k * 32 + j]), o);
    }
    out[tid] = sigm(o);
}

// ---------------- launch ----------------
extern "C" void kernel_launch(void* const* d_in, const int* in_sizes, int n_in,
                              void* d_out, int out_size) {
    const void* p_x = 0;  const void* p_ei = 0; const void* p_ea = 0;
    const void* p_W1 = 0; const void* p_b1 = 0; const void* p_W2 = 0;
    const void* p_b2 = 0; const void* p_W3 = 0; const void* p_b3 = 0;
    for (int i = 0; i < n_in; i++) {
        int s = in_sizes[i];
        const void* p = d_in[i];
        if      (s == NB * NNODES * NIN)  p_x = p;
        else if (s == 2 * NEDGES)         p_ei = p;
        else if (s == NEDGES)             p_ea = p;
        else if (s == (2 * NIN + 1) * 32) p_W1 = p;
        else if (s == 32 * H2)            { if (!p_W2) p_W2 = p; else p_W3 = p; }
        else if (s == 32)                 { if (!p_b1) p_b1 = p; else p_b3 = p; }
        else if (s == H2)                 p_b2 = p;
    }
    const float* x  = (const float*)p_x;
    const int*   ei = (const int*)p_ei;
    const float* ea = (const float*)p_ea;
    const float* W1 = (const float*)p_W1;
    const float* b1 = (const float*)p_b1;
    const float* W2 = (const float*)p_W2;
    const float* b2 = (const float*)p_b2;
    const float* W3 = (const float*)p_W3;
    const float* b3 = (const float*)p_b3;
    float* out = (float*)d_out;

    k_detect<<<1, 1>>>(ei);                                              // 1
    k_convert<<<(NEDGES + 255) / 256, 256>>>(ei);                        // 2
    k_reduce_ea<<<(NEDGES + 255) / 256, 256>>>(ea);                      // 3
    k_finalize_stats<<<1, 1>>>();                                        // 4
    k_precompute<<<(NB * NNODES * 32 + 255) / 256, 256>>>(x, W1, b1);    // 5
    dim3 egrid((NEDGES + 255) / 256, NB);
    k_edge<<<egrid, 256>>>(ea, W1, W2, b2);                              // 6  <- ncu -s 5 -c 1
    k_out<<<(NB * NNODES * 32 + 255) / 256, 256>>>(W3, b3, out);         // 7
}